// round 13
// baseline (speedup 1.0000x reference)
#include <cuda_runtime.h>

#define NB     256      // batches
#define NQ     1000     // queries
#define NC     80       // classes
#define QC     80000    // NQ*NC
#define K      300      // top-k
#define NV     (QC / 4) // 20000 float4 per batch

#define SLICES    8
#define ROLES     9               // 8 scan slices + 1 rank spinner per batch
#define SLICE_F4  (NV / SLICES)   // 2500 float4 per slice
#define SLICE_CAP 384
#define RCAP      1024            // candidate capacity
#define NBINS     512
#define FSHIFT    15              // fixed window: 512<<15 keys above kmin (~2.58..10.3)

#define NTH   256
#define HPT   (RCAP / NTH)        // 4 candidates per thread

#define THRESH 2.576f   // P(N(0,1)>2.576) ~ 0.5% -> ~400 cands/batch

// global scratch (allowed: __device__ arrays, no allocation); self-resetting
__device__ unsigned long long g_cand[NB][SLICES][SLICE_CAP];
__device__ unsigned           g_scnt[NB][SLICES];
__device__ unsigned           g_done[NB];      // zero-init; spinner resets after consume

// order-preserving float -> uint key (larger key == larger float)
__device__ __forceinline__ unsigned key_of(float x) {
    unsigned u = __float_as_uint(x);
    return (u & 0x80000000u) ? ~u : (u | 0x80000000u);
}
__device__ __forceinline__ float val_of(unsigned k) {
    unsigned u = (k & 0x80000000u) ? (k ^ 0x80000000u) : ~k;
    return __uint_as_float(u);
}

__global__ __launch_bounds__(NTH, 8)
void fused_kernel(const float* __restrict__ logits,
                  const float* __restrict__ boxes,
                  const float* __restrict__ sizes,
                  float* __restrict__ out)
{
    __shared__ unsigned long long buf[RCAP];
    __shared__ unsigned cnt_ge[NBINS + 1];
    __shared__ unsigned offs[SLICES + 1];
    __shared__ unsigned wtot[NTH / 32], wsuf[NTH / 32];
    __shared__ int      s_bad;
    __shared__ unsigned s_cnt;
    __shared__ unsigned s_kmax;

    const int b    = blockIdx.x / ROLES;    // batch
    const int role = blockIdx.x % ROLES;    // 0..7 scan slice, 8 rank
    const int tid  = threadIdx.x;
    const int lane = tid & 31;
    const int wid  = tid >> 5;

    const unsigned KMIN = key_of(THRESH);

    // ================= role 0..7: skinny scan slice =================
    if (role < SLICES) {
        const int s = role;
        if (tid == 0) s_cnt = 0;
        __syncthreads();

        const float4* base = (const float4*)(logits + (size_t)b * QC) + s * SLICE_F4;
        #pragma unroll 5
        for (int i = tid; i < SLICE_F4; i += NTH) {
            float4 v = base[i];
            float m01 = fmaxf(v.x, v.y);
            float m23 = fmaxf(v.z, v.w);
            if (fmaxf(m01, m23) > THRESH) {          // rare (~2% of iters)
                float xs[4] = {v.x, v.y, v.z, v.w};
                #pragma unroll
                for (int j = 0; j < 4; j++) {
                    if (xs[j] > THRESH) {
                        unsigned p = atomicAdd(&s_cnt, 1u);
                        if (p < SLICE_CAP) {
                            unsigned idx = 4u * (unsigned)(s * SLICE_F4 + i) + (unsigned)j;
                            g_cand[b][s][p] = ((unsigned long long)key_of(xs[j]) << 32)
                                            | (unsigned long long)(~idx);
                        }
                    }
                }
            }
        }
        __syncthreads();
        if (tid == 0) {
            g_scnt[b][s] = s_cnt;
            __threadfence();
            atomicAdd(&g_done[b], 1u);
        }
        return;
    }

    // ================= role 8: rank spinner =================
    if (tid == 0) {
        // wait for all 8 slices of this batch (nanosleep backoff; L2 atomic read)
        while (atomicAdd(&g_done[b], 0u) < SLICES) __nanosleep(100);
        g_done[b] = 0;   // consume: reset for next graph replay
    }
    __syncthreads();
    __threadfence();     // acquire: slices' g_cand/g_scnt writes visible

    unsigned M;
    unsigned kmin = KMIN;
    int shift = FSHIFT;

    if (tid == 0) {
        unsigned sum = 0; int bad = 0;
        #pragma unroll
        for (int s2 = 0; s2 < SLICES; s2++) {
            unsigned c = g_scnt[b][s2];
            if (c > SLICE_CAP) bad = 1;
            offs[s2] = sum;
            sum += min(c, (unsigned)SLICE_CAP);
        }
        offs[SLICES] = sum;
        if (sum < K || sum > RCAP) bad = 1;
        s_bad = bad;
        s_kmax = 0;
    }
    for (int i = tid; i < NBINS; i += NTH) cnt_ge[i] = 0;
    __syncthreads();

    bool from_smem = false;
    unsigned long long comp[HPT];
    unsigned binv[HPT];
    bool act[HPT];

    if (!s_bad) {
        M = offs[SLICES];
        // direct global->register candidate loads (4 independent LDGs) + histogram
        #pragma unroll
        for (int h = 0; h < HPT; h++) {
            unsigned i = (unsigned)tid + h * NTH;
            act[h] = (i < M);
            if (act[h]) {
                int s2 = 0;
                #pragma unroll
                for (int t = 1; t < SLICES; t++) s2 += (i >= offs[t]);
                comp[h] = g_cand[b][s2][i - offs[s2]];
            }
        }
        #pragma unroll
        for (int h = 0; h < HPT; h++) {
            if (act[h]) {
                unsigned key = (unsigned)(comp[h] >> 32);
                binv[h] = min((key - kmin) >> FSHIFT, (unsigned)(NBINS - 1));
                atomicAdd(&cnt_ge[binv[h]], 1u);
            }
        }
        __syncthreads();
    } else {
        // fallback: full-batch bisection rescan (correct for any distribution)
        const float4* base = (const float4*)(logits + (size_t)b * QC);
        unsigned lo_key = 0u, hi_key = 0xFFFFFFFFu;
        unsigned cur = KMIN;
        M = 0;
        for (int attempt = 0; attempt < 34; attempt++) {
            if (tid == 0) s_cnt = 0;
            __syncthreads();
            const float t = val_of(cur);
            for (int i = tid; i < NV; i += NTH) {
                float4 v = base[i];
                float m01 = fmaxf(v.x, v.y);
                float m23 = fmaxf(v.z, v.w);
                if (fmaxf(m01, m23) > t) {
                    float xs[4] = {v.x, v.y, v.z, v.w};
                    #pragma unroll
                    for (int j = 0; j < 4; j++) {
                        if (xs[j] > t) {
                            unsigned p = atomicAdd(&s_cnt, 1u);
                            if (p < RCAP) {
                                unsigned idx = 4u * (unsigned)i + (unsigned)j;
                                buf[p] = ((unsigned long long)key_of(xs[j]) << 32)
                                       | (unsigned long long)(~idx);
                            }
                        }
                    }
                }
            }
            __syncthreads();
            unsigned tot = s_cnt;
            if (tot >= K && tot <= RCAP) { M = tot; kmin = cur; break; }
            __syncthreads();
            if (tot > RCAP) { lo_key = cur; cur = cur + ((hi_key - cur) >> 1); }
            else            { hi_key = cur; cur = lo_key + ((cur - lo_key) >> 1); }
        }
        if (M == 0) { M = min(s_cnt, (unsigned)RCAP); kmin = 0u; }
        __syncthreads();
        // adaptive shift over fallback candidates
        {
            unsigned km = 0;
            for (unsigned i = tid; i < M; i += NTH)
                km = max(km, (unsigned)(buf[i] >> 32));
            km = __reduce_max_sync(0xFFFFFFFFu, km);
            if (lane == 0) atomicMax(&s_kmax, km);
        }
        for (int i = tid; i < NBINS; i += NTH) cnt_ge[i] = 0;
        __syncthreads();
        unsigned range = s_kmax - kmin;
        if (range == 0) range = 1;
        shift = 32 - __clz(range) - 9;   // (range>>shift) <= 511
        if (shift < 0) shift = 0;
        #pragma unroll
        for (int h = 0; h < HPT; h++) {
            unsigned i = (unsigned)tid + h * NTH;
            act[h] = (i < M);
            if (act[h]) {
                comp[h] = buf[i];
                unsigned key = (unsigned)(comp[h] >> 32);
                binv[h] = min((key - kmin) >> shift, (unsigned)(NBINS - 1));
                atomicAdd(&cnt_ge[binv[h]], 1u);
            }
        }
        from_smem = true;
        __syncthreads();
    }
    (void)from_smem;

    // ---- suffix scan of 512 bins: 2 bins/thread, warp-shuffle, 3 barriers ----
    {
        unsigned b0 = cnt_ge[2 * tid];
        unsigned b1 = cnt_ge[2 * tid + 1];
        unsigned v  = b0 + b1;
        #pragma unroll
        for (int d = 1; d < 32; d <<= 1) {
            unsigned o = __shfl_down_sync(0xFFFFFFFFu, v, d);
            if (lane + d < 32) v += o;
        }
        if (lane == 0) wtot[wid] = v;
        __syncthreads();
        if (tid == 0) {
            unsigned run = 0;
            #pragma unroll
            for (int w = NTH / 32 - 1; w >= 0; w--) {
                unsigned t2 = wtot[w];
                wsuf[w] = run;
                run += t2;
            }
        }
        __syncthreads();
        unsigned suf = v + wsuf[wid];       // # candidates in bins >= 2*tid
        cnt_ge[2 * tid]     = suf;
        cnt_ge[2 * tid + 1] = suf - b0;
        if (tid == 0) cnt_ge[NBINS] = 0;
    }
    __syncthreads();

    // ---- read base/cnt BEFORE scatter mutates cnt_ge ----
    unsigned basep[HPT], cntb[HPT];
    #pragma unroll
    for (int h = 0; h < HPT; h++) {
        if (act[h]) {
            basep[h] = cnt_ge[binv[h] + 1];            // # in strictly higher bins
            cntb[h]  = cnt_ge[binv[h]] - basep[h];     // # in my bin
        }
    }
    __syncthreads();

    // ---- scatter into bin-grouped order (sources register-held) ----
    #pragma unroll
    for (int h = 0; h < HPT; h++) {
        if (act[h]) {
            unsigned p = atomicAdd(&cnt_ge[binv[h] + 1], 1u);   // in [base, base+cntb)
            buf[p] = comp[h];
        }
    }
    __syncthreads();

    // ---- exact rank = base + #{same-bin > mine}; emit if < K ----
    const float w = sizes[2 * b], h2 = sizes[2 * b + 1];
    #pragma unroll
    for (int h = 0; h < HPT; h++) {
        if (act[h] && basep[h] < K) {
            unsigned r = basep[h];
            unsigned e = basep[h] + cntb[h];
            for (unsigned j = basep[h]; j < e; j++)
                r += (buf[j] > comp[h]);
            if (r < K) {
                unsigned kk  = (unsigned)(comp[h] >> 32);
                unsigned idx = ~(unsigned)comp[h];
                float x = val_of(kk);
                float score = 1.0f / (1.0f + expf(-x));
                int label = (int)(idx % NC);
                int q     = (int)(idx / NC);

                float4 bx = ((const float4*)(boxes + ((size_t)b * NQ + q) * 4))[0];
                float hw = 0.5f * bx.z, hh = 0.5f * bx.w;

                int o = b * K + (int)r;
                out[o] = (float)label;                     // labels [B,K]
                float* ob = out + NB * K + (size_t)o * 4;  // boxes  [B,K,4]
                ob[0] = (bx.x - hw) * w;
                ob[1] = (bx.y - hh) * h2;
                ob[2] = (bx.x + hw) * w;
                ob[3] = (bx.y + hh) * h2;
                out[(size_t)NB * K * 5 + o] = score;       // scores [B,K]
            }
        }
    }
}

extern "C" void kernel_launch(void* const* d_in, const int* in_sizes, int n_in,
                              void* d_out, int out_size) {
    const float* logits = (const float*)d_in[0];
    const float* boxes  = (const float*)d_in[1];
    const float* sizes  = (const float*)d_in[2];
    float* out = (float*)d_out;
    fused_kernel<<<NB * ROLES, NTH>>>(logits, boxes, sizes, out);
}

// round 16
// speedup vs baseline: 1.0405x; 1.0405x over previous
#include <cuda_runtime.h>
#include <cstdint>

#define NB     256      // batches
#define NQ     1000     // queries
#define NC     80       // classes
#define QC     80000    // NQ*NC
#define K      300      // top-k
#define NV     (QC / 4) // 20000 float4 per batch

#define SLICES    8
#define NTASK     (NB * SLICES)   // 2048 slice tasks
#define NCTA      1024            // one full wave; each CTA scans 2 tasks
#define SLICE_F4  (NV / SLICES)   // 2500 float4 per slice
#define SLICE_CAP 384
#define RCAP      1024            // candidate capacity
#define NBINS     512
#define FSHIFT    15              // fixed window: 512<<15 keys above kmin (~2.58..10.3)

#define NTH   256
#define HPT   (RCAP / NTH)        // 4 candidate slots per thread

#define THRESH 2.576f   // P(N(0,1)>2.576) ~ 0.5% -> ~400 cands/batch

// global scratch (allowed: __device__ arrays, no allocation); self-resetting
__device__ unsigned long long g_cand[NB][SLICES][SLICE_CAP];
__device__ unsigned           g_scnt[NB][SLICES];
__device__ unsigned           g_done[NB];   // zero-init; ranker resets after consume

// order-preserving float -> uint key (larger key == larger float)
__device__ __forceinline__ unsigned key_of(float x) {
    unsigned u = __float_as_uint(x);
    return (u & 0x80000000u) ? ~u : (u | 0x80000000u);
}
__device__ __forceinline__ float val_of(unsigned k) {
    unsigned u = (k & 0x80000000u) ? (k ^ 0x80000000u) : ~k;
    return __uint_as_float(u);
}

__global__ __launch_bounds__(NTH, 8)
void fused_kernel(const float* __restrict__ logits,
                  const float* __restrict__ boxes,
                  const float* __restrict__ sizes,
                  float* __restrict__ out)
{
    __shared__ unsigned long long buf[RCAP];
    __shared__ unsigned cnt_ge[NBINS + 1];
    __shared__ unsigned offs[SLICES + 1];
    __shared__ unsigned wtot[NTH / 32], wsuf[NTH / 32];
    __shared__ int      s_bad;
    __shared__ unsigned s_cnt;
    __shared__ unsigned s_kmax;

    const int c    = blockIdx.x;
    const int tid  = threadIdx.x;
    const int lane = tid & 31;
    const int wid  = tid >> 5;

    const unsigned KMIN = key_of(THRESH);

    // ================= phase 1: scan my 2 slice-tasks (roofline loop) =================
    #pragma unroll
    for (int t = c; t < NTASK; t += NCTA) {
        const int tb = t >> 3;          // batch of this task
        const int ts = t & 7;           // slice of this task
        if (tid == 0) s_cnt = 0;
        __syncthreads();

        const float4* base = (const float4*)(logits + (size_t)tb * QC) + ts * SLICE_F4;
        #pragma unroll 5
        for (int i = tid; i < SLICE_F4; i += NTH) {
            float4 v = base[i];
            float m01 = fmaxf(v.x, v.y);
            float m23 = fmaxf(v.z, v.w);
            if (fmaxf(m01, m23) > THRESH) {          // rare (~2% of iters)
                float xs[4] = {v.x, v.y, v.z, v.w};
                #pragma unroll
                for (int j = 0; j < 4; j++) {
                    if (xs[j] > THRESH) {
                        unsigned p = atomicAdd(&s_cnt, 1u);
                        if (p < SLICE_CAP) {
                            unsigned idx = 4u * (unsigned)(ts * SLICE_F4 + i) + (unsigned)j;
                            g_cand[tb][ts][p] = ((unsigned long long)key_of(xs[j]) << 32)
                                              | (unsigned long long)(~idx);
                        }
                    }
                }
            }
        }
        __syncthreads();
        if (tid == 0) {
            g_scnt[tb][ts] = s_cnt;
            __threadfence();
            atomicAdd(&g_done[tb], 1u);
        }
        __syncthreads();
    }

    // ================= phase 2: CTAs 0..NB-1 rank their designated batch =================
    if (c >= NB) return;
    const int b = c;

    if (tid == 0) {
        while (atomicAdd(&g_done[b], 0u) < SLICES) __nanosleep(100);
        g_done[b] = 0;   // consume: reset for next graph replay
    }
    __syncthreads();
    __threadfence();     // acquire: all slices' candidate/count writes visible

    unsigned M;
    unsigned kmin = KMIN;
    int shift = FSHIFT;

    if (tid == 0) {
        unsigned sum = 0; int bad = 0;
        #pragma unroll
        for (int s2 = 0; s2 < SLICES; s2++) {
            unsigned cc = g_scnt[b][s2];
            if (cc > SLICE_CAP) bad = 1;
            offs[s2] = sum;
            sum += min(cc, (unsigned)SLICE_CAP);
        }
        offs[SLICES] = sum;
        if (sum < K || sum > RCAP) bad = 1;
        s_bad = bad;
        s_kmax = 0;
    }
    for (int i = tid; i < NBINS; i += NTH) cnt_ge[i] = 0;
    __syncthreads();

    unsigned long long comp[HPT];
    unsigned binv[HPT];
    bool act[HPT];

    if (!s_bad) {
        M = offs[SLICES];
        // direct global->register candidate loads (4 independent LDGs) + histogram
        #pragma unroll
        for (int h = 0; h < HPT; h++) {
            unsigned i = (unsigned)tid + h * NTH;
            act[h] = (i < M);
            if (act[h]) {
                int s2 = 0;
                #pragma unroll
                for (int t2 = 1; t2 < SLICES; t2++) s2 += (i >= offs[t2]);
                comp[h] = g_cand[b][s2][i - offs[s2]];
            }
        }
        #pragma unroll
        for (int h = 0; h < HPT; h++) {
            if (act[h]) {
                unsigned key = (unsigned)(comp[h] >> 32);
                binv[h] = min((key - kmin) >> FSHIFT, (unsigned)(NBINS - 1));
                atomicAdd(&cnt_ge[binv[h]], 1u);
            }
        }
        __syncthreads();
    } else {
        // fallback: full-batch bisection rescan (correct for any distribution)
        const float4* base = (const float4*)(logits + (size_t)b * QC);
        unsigned lo_key = 0u, hi_key = 0xFFFFFFFFu;
        unsigned cur = KMIN;
        M = 0;
        for (int attempt = 0; attempt < 34; attempt++) {
            if (tid == 0) s_cnt = 0;
            __syncthreads();
            const float t = val_of(cur);
            for (int i = tid; i < NV; i += NTH) {
                float4 v = base[i];
                float m01 = fmaxf(v.x, v.y);
                float m23 = fmaxf(v.z, v.w);
                if (fmaxf(m01, m23) > t) {
                    float xs[4] = {v.x, v.y, v.z, v.w};
                    #pragma unroll
                    for (int j = 0; j < 4; j++) {
                        if (xs[j] > t) {
                            unsigned p = atomicAdd(&s_cnt, 1u);
                            if (p < RCAP) {
                                unsigned idx = 4u * (unsigned)i + (unsigned)j;
                                buf[p] = ((unsigned long long)key_of(xs[j]) << 32)
                                       | (unsigned long long)(~idx);
                            }
                        }
                    }
                }
            }
            __syncthreads();
            unsigned tot = s_cnt;
            if (tot >= K && tot <= RCAP) { M = tot; kmin = cur; break; }
            __syncthreads();
            if (tot > RCAP) { lo_key = cur; cur = cur + ((hi_key - cur) >> 1); }
            else            { hi_key = cur; cur = lo_key + ((cur - lo_key) >> 1); }
        }
        if (M == 0) { M = min(s_cnt, (unsigned)RCAP); kmin = 0u; }
        __syncthreads();
        // adaptive shift over fallback candidates
        {
            unsigned km = 0;
            for (unsigned i = tid; i < M; i += NTH)
                km = max(km, (unsigned)(buf[i] >> 32));
            km = __reduce_max_sync(0xFFFFFFFFu, km);
            if (lane == 0) atomicMax(&s_kmax, km);
        }
        for (int i = tid; i < NBINS; i += NTH) cnt_ge[i] = 0;
        __syncthreads();
        unsigned range = s_kmax - kmin;
        if (range == 0) range = 1;
        shift = 32 - __clz(range) - 9;   // (range>>shift) <= 511
        if (shift < 0) shift = 0;
        #pragma unroll
        for (int h = 0; h < HPT; h++) {
            unsigned i = (unsigned)tid + h * NTH;
            act[h] = (i < M);
            if (act[h]) {
                comp[h] = buf[i];
                unsigned key = (unsigned)(comp[h] >> 32);
                binv[h] = min((key - kmin) >> shift, (unsigned)(NBINS - 1));
                atomicAdd(&cnt_ge[binv[h]], 1u);
            }
        }
        __syncthreads();
    }

    // ---- suffix scan of 512 bins: 2 bins/thread, warp-shuffle, 3 barriers ----
    {
        unsigned b0 = cnt_ge[2 * tid];
        unsigned b1 = cnt_ge[2 * tid + 1];
        unsigned v  = b0 + b1;
        #pragma unroll
        for (int d = 1; d < 32; d <<= 1) {
            unsigned o = __shfl_down_sync(0xFFFFFFFFu, v, d);
            if (lane + d < 32) v += o;
        }
        if (lane == 0) wtot[wid] = v;
        __syncthreads();
        if (tid == 0) {
            unsigned run = 0;
            #pragma unroll
            for (int w = NTH / 32 - 1; w >= 0; w--) {
                unsigned t2 = wtot[w];
                wsuf[w] = run;
                run += t2;
            }
        }
        __syncthreads();
        unsigned suf = v + wsuf[wid];       // # candidates in bins >= 2*tid
        cnt_ge[2 * tid]     = suf;
        cnt_ge[2 * tid + 1] = suf - b0;
        if (tid == 0) cnt_ge[NBINS] = 0;
    }
    __syncthreads();

    // ---- read base/cnt BEFORE scatter mutates cnt_ge ----
    unsigned basep[HPT], cntb[HPT];
    #pragma unroll
    for (int h = 0; h < HPT; h++) {
        if (act[h]) {
            basep[h] = cnt_ge[binv[h] + 1];            // # in strictly higher bins
            cntb[h]  = cnt_ge[binv[h]] - basep[h];     // # in my bin
        }
    }
    __syncthreads();

    // ---- scatter into bin-grouped order (sources register-held) ----
    #pragma unroll
    for (int h = 0; h < HPT; h++) {
        if (act[h]) {
            unsigned p = atomicAdd(&cnt_ge[binv[h] + 1], 1u);   // in [base, base+cntb)
            buf[p] = comp[h];
        }
    }
    __syncthreads();

    // ---- exact rank = base + #{same-bin > mine}; emit if < K ----
    const float w = sizes[2 * b], h2 = sizes[2 * b + 1];
    #pragma unroll
    for (int h = 0; h < HPT; h++) {
        if (act[h] && basep[h] < K) {
            unsigned r = basep[h];
            unsigned e = basep[h] + cntb[h];
            for (unsigned j = basep[h]; j < e; j++)
                r += (buf[j] > comp[h]);
            if (r < K) {
                unsigned kk  = (unsigned)(comp[h] >> 32);
                unsigned idx = ~(unsigned)comp[h];
                float x = val_of(kk);
                float score = 1.0f / (1.0f + expf(-x));
                int label = (int)(idx % NC);
                int q     = (int)(idx / NC);

                float4 bx = ((const float4*)(boxes + ((size_t)b * NQ + q) * 4))[0];
                float hw = 0.5f * bx.z, hh = 0.5f * bx.w;

                int o = b * K + (int)r;
                out[o] = (float)label;                     // labels [B,K]
                float* ob = out + NB * K + (size_t)o * 4;  // boxes  [B,K,4]
                ob[0] = (bx.x - hw) * w;
                ob[1] = (bx.y - hh) * h2;
                ob[2] = (bx.x + hw) * w;
                ob[3] = (bx.y + hh) * h2;
                out[(size_t)NB * K * 5 + o] = score;       // scores [B,K]
            }
        }
    }
}

extern "C" void kernel_launch(void* const* d_in, const int* in_sizes, int n_in,
                              void* d_out, int out_size) {
    const float* logits = (const float*)d_in[0];
    const float* boxes  = (const float*)d_in[1];
    const float* sizes  = (const float*)d_in[2];
    float* out = (float*)d_out;
    fused_kernel<<<NCTA, NTH>>>(logits, boxes, sizes, out);
}